// round 4
// baseline (speedup 1.0000x reference)
#include <cuda_runtime.h>
#include <cuda_bf16.h>
#include <mma.h>

using namespace nvcuda;

#define MAX_N 50000
#define MAX_E 800000
#define D_NODE 192
#define D_EDGE 64
#define D_IN 256
#define D_OUT 256

// ---------------- scratch (device globals: no allocations allowed) ----------
__device__ float g_h[(size_t)MAX_N * D_IN];      // 51.2 MB aggregated+scaled features
__device__ int   g_outdeg[MAX_N];
__device__ int   g_indeg[MAX_N];
__device__ int   g_starts[MAX_N];
__device__ int   g_cursor[MAX_N];
__device__ int   g_bucket[MAX_E];
__device__ float g_outscale[MAX_N];
__device__ float g_inscale[MAX_N];
__device__ int   g_total;                        // range-allocation cursor

// ---------------- K1: zero counters ----------------------------------------
__global__ void zero_kernel(int N) {
    int i = blockIdx.x * blockDim.x + threadIdx.x;
    if (i < N) {
        g_outdeg[i] = 0;
        g_indeg[i]  = 0;
        g_cursor[i] = 0;
    }
    if (i == 0) g_total = 0;
}

// ---------------- K2: degree histograms -------------------------------------
__global__ void degree_kernel(const int* __restrict__ src,
                              const int* __restrict__ dst, int E) {
    int e = blockIdx.x * blockDim.x + threadIdx.x;
    if (e < E) {
        atomicAdd(&g_outdeg[src[e]], 1);
        atomicAdd(&g_indeg[dst[e]], 1);
    }
}

// ---------------- K3: per-node range allocation + scales ---------------------
// Bucket ranges need only be disjoint & contiguous per node — NOT node-ordered.
// Warp shuffle-scan + one atomicAdd per warp replaces a serial block scan.
__global__ void offsets_kernel(int N) {
    int i = blockIdx.x * blockDim.x + threadIdx.x;
    int lane = threadIdx.x & 31;
    int v = (i < N) ? g_indeg[i] : 0;
    if (i < N) {
        g_inscale[i]  = rsqrtf(fmaxf((float)v, 1.0f));
        g_outscale[i] = rsqrtf(fmaxf((float)g_outdeg[i], 1.0f));
    }
    // warp inclusive scan of v
    int incl = v;
#pragma unroll
    for (int off = 1; off < 32; off <<= 1) {
        int x = __shfl_up_sync(0xffffffffu, incl, off);
        if (lane >= off) incl += x;
    }
    int warp_sum = __shfl_sync(0xffffffffu, incl, 31);
    int base = 0;
    if (lane == 31) base = atomicAdd(&g_total, warp_sum);
    base = __shfl_sync(0xffffffffu, base, 31);
    if (i < N) g_starts[i] = base + incl - v;
}

// ---------------- K4: bucket fill (counting sort by dst) --------------------
__global__ void bucket_kernel(const int* __restrict__ dst, int E) {
    int e = blockIdx.x * blockDim.x + threadIdx.x;
    if (e < E) {
        int d = dst[e];
        int pos = atomicAdd(&g_cursor[d], 1);
        g_bucket[g_starts[d] + pos] = e;
    }
}

// ---------------- K5: pull-style gather (warp per dst node) ------------------
// h[n, 0:192]   = in_scale[n] * sum_e out_scale[src] * feat[src]
// h[n, 192:256] = in_scale[n] * sum_e edge_feat[e]
// lane l: accA = cols [4l,4l+4);  accB = cols [128+4l, 128+4l+4)
__global__ void gather_kernel(const float* __restrict__ feat,
                              const float* __restrict__ edge_feat,
                              const int* __restrict__ src,
                              int N) {
    int warp = (blockIdx.x * blockDim.x + threadIdx.x) >> 5;
    int lane = threadIdx.x & 31;
    if (warp >= N) return;

    int beg = g_starts[warp];
    int cnt = g_indeg[warp];

    float4 accA = make_float4(0.f, 0.f, 0.f, 0.f);
    float4 accB = make_float4(0.f, 0.f, 0.f, 0.f);

    for (int i = 0; i < cnt; i++) {
        int e = g_bucket[beg + i];            // warp-uniform broadcast
        int s = src[e];
        float sc = g_outscale[s];
        const float4* frow = (const float4*)(feat + (size_t)s * D_NODE);
        float4 a = __ldg(&frow[lane]);        // cols 0..127
        accA.x += a.x * sc; accA.y += a.y * sc;
        accA.z += a.z * sc; accA.w += a.w * sc;

        float4 b; float bs;
        if (lane < 16) {                       // cols 128..191 (feat part)
            b = __ldg(&frow[32 + lane]);
            bs = sc;
        } else {                               // cols 192..255 (edge part)
            const float4* erow = (const float4*)(edge_feat + (size_t)e * D_EDGE);
            b = __ldg(&erow[lane - 16]);
            bs = 1.0f;
        }
        accB.x += b.x * bs; accB.y += b.y * bs;
        accB.z += b.z * bs; accB.w += b.w * bs;
    }

    float is = g_inscale[warp];               // fold post-GEMM row scaling here
    accA.x *= is; accA.y *= is; accA.z *= is; accA.w *= is;
    accB.x *= is; accB.y *= is; accB.z *= is; accB.w *= is;

    float4* hrow = (float4*)(g_h + (size_t)warp * D_IN);
    hrow[lane]      = accA;
    hrow[32 + lane] = accB;
}

// ---------------- K6: GEMM  out = g_h @ W + bias  (split-bf16, 3-pass) -------
// Block: 256 thr = 8 warps (4 in M x 2 in N); block tile 128x64; warp 32x32.
// NOTE: g_h referenced directly from device code (a __device__ symbol's name is
// NOT a valid device pointer in host code — that was the round-3 bug).
#define AS 40   // A smem stride (bf16 elems), multiple of 8
#define BS 72   // B smem stride
#define CS 68   // C smem stride (floats), multiple of 4
#define KCHUNK 32

__global__ __launch_bounds__(256) void gemm_kernel(const float* __restrict__ W,
                                                   const float* __restrict__ bias,
                                                   float* __restrict__ out, int M) {
    __shared__ __align__(16) unsigned char smem_raw[128 * CS * sizeof(float)]; // 34816 B
    __nv_bfloat16* Ah = (__nv_bfloat16*)smem_raw;
    __nv_bfloat16* Al = Ah + 128 * AS;
    __nv_bfloat16* Bh = Al + 128 * AS;
    __nv_bfloat16* Bl = Bh + KCHUNK * BS;
    float* Cs = (float*)smem_raw;

    const float* __restrict__ H = g_h;

    int t = threadIdx.x;
    int warpId = t >> 5;
    int wm = warpId & 3;       // 0..3 -> rows wm*32
    int wn = warpId >> 2;      // 0..1 -> cols wn*32
    int m0 = blockIdx.x * 128;
    int n0 = blockIdx.y * 64;

    wmma::fragment<wmma::accumulator, 16, 16, 16, float> acc[2][2];
#pragma unroll
    for (int i = 0; i < 2; i++)
#pragma unroll
        for (int j = 0; j < 2; j++) wmma::fill_fragment(acc[i][j], 0.0f);

    for (int kc = 0; kc < D_IN; kc += KCHUNK) {
        __syncthreads();
        // stage A 128x32 (split into hi/lo bf16)
#pragma unroll
        for (int r = 0; r < 16; r++) {
            int idx = t + 256 * r;
            int row = idx >> 5, col = idx & 31;
            int gm = m0 + row;
            float v = (gm < M) ? H[(size_t)gm * D_IN + kc + col] : 0.0f;
            __nv_bfloat16 hi = __float2bfloat16(v);
            Ah[row * AS + col] = hi;
            Al[row * AS + col] = __float2bfloat16(v - __bfloat162float(hi));
        }
        // stage B 32x64
#pragma unroll
        for (int r = 0; r < 8; r++) {
            int idx = t + 256 * r;
            int row = idx >> 6, col = idx & 63;
            float v = W[(size_t)(kc + row) * D_OUT + n0 + col];
            __nv_bfloat16 hi = __float2bfloat16(v);
            Bh[row * BS + col] = hi;
            Bl[row * BS + col] = __float2bfloat16(v - __bfloat162float(hi));
        }
        __syncthreads();

#pragma unroll
        for (int kk = 0; kk < KCHUNK; kk += 16) {
            wmma::fragment<wmma::matrix_a, 16, 16, 16, __nv_bfloat16, wmma::row_major> fah[2], fal[2];
            wmma::fragment<wmma::matrix_b, 16, 16, 16, __nv_bfloat16, wmma::row_major> fbh[2], fbl[2];
#pragma unroll
            for (int i = 0; i < 2; i++) {
                const __nv_bfloat16* pa = Ah + (wm * 32 + i * 16) * AS + kk;
                const __nv_bfloat16* pl = Al + (wm * 32 + i * 16) * AS + kk;
                wmma::load_matrix_sync(fah[i], pa, AS);
                wmma::load_matrix_sync(fal[i], pl, AS);
            }
#pragma unroll
            for (int j = 0; j < 2; j++) {
                const __nv_bfloat16* pb = Bh + kk * BS + wn * 32 + j * 16;
                const __nv_bfloat16* pl = Bl + kk * BS + wn * 32 + j * 16;
                wmma::load_matrix_sync(fbh[j], pb, BS);
                wmma::load_matrix_sync(fbl[j], pl, BS);
            }
#pragma unroll
            for (int i = 0; i < 2; i++)
#pragma unroll
                for (int j = 0; j < 2; j++) {
                    wmma::mma_sync(acc[i][j], fal[i], fbh[j], acc[i][j]);
                    wmma::mma_sync(acc[i][j], fah[i], fbl[j], acc[i][j]);
                    wmma::mma_sync(acc[i][j], fah[i], fbh[j], acc[i][j]);
                }
        }
    }

    // epilogue: frag -> smem -> global (+bias)
    __syncthreads();
#pragma unroll
    for (int i = 0; i < 2; i++)
#pragma unroll
        for (int j = 0; j < 2; j++)
            wmma::store_matrix_sync(Cs + (wm * 32 + i * 16) * CS + wn * 32 + j * 16,
                                    acc[i][j], CS, wmma::mem_row_major);
    __syncthreads();
#pragma unroll
    for (int r = 0; r < 32; r++) {
        int idx = t + 256 * r;
        int row = idx >> 6, col = idx & 63;
        int gm = m0 + row;
        if (gm < M) out[(size_t)gm * D_OUT + n0 + col] = Cs[row * CS + col] + bias[n0 + col];
    }
}

// ---------------- launch -----------------------------------------------------
extern "C" void kernel_launch(void* const* d_in, const int* in_sizes, int n_in,
                              void* d_out, int out_size) {
    const float* feat      = (const float*)d_in[0];
    const float* edge_feat = (const float*)d_in[1];
    const int*   src       = (const int*)d_in[2];
    const int*   dst       = (const int*)d_in[3];
    const float* weight    = (const float*)d_in[4];
    const float* bias      = (const float*)d_in[5];
    float* out = (float*)d_out;

    int N = in_sizes[0] / D_NODE;   // 50000
    int E = in_sizes[2];            // 800000

    zero_kernel<<<(N + 255) / 256, 256>>>(N);
    degree_kernel<<<(E + 255) / 256, 256>>>(src, dst, E);
    offsets_kernel<<<(N + 255) / 256, 256>>>(N);
    bucket_kernel<<<(E + 255) / 256, 256>>>(dst, E);
    gather_kernel<<<(N * 32 + 255) / 256, 256>>>(feat, edge_feat, src, N);

    dim3 ggrid((N + 127) / 128, D_OUT / 64);
    gemm_kernel<<<ggrid, 256>>>(weight, bias, out, N);
}

// round 7
// speedup vs baseline: 1.3873x; 1.3873x over previous
#include <cuda_runtime.h>
#include <cuda_bf16.h>
#include <mma.h>

using namespace nvcuda;

#define MAX_N 50000
#define MAX_E 800000
#define D_NODE 192
#define D_EDGE 64
#define D_IN 256
#define D_OUT 256

// ---------------- scratch (device globals: no allocations allowed) ----------
__device__ __nv_bfloat16 g_hh[(size_t)MAX_N * D_IN];   // hi split of h (25.6MB)
__device__ __nv_bfloat16 g_hl[(size_t)MAX_N * D_IN];   // lo split of h
__device__ __nv_bfloat16 g_wh[D_IN * D_OUT];           // hi split of W
__device__ __nv_bfloat16 g_wl[D_IN * D_OUT];           // lo split of W
__device__ int   g_outdeg[MAX_N];
__device__ int   g_indeg[MAX_N];
__device__ int   g_starts[MAX_N];
__device__ int   g_cursor[MAX_N];
__device__ int   g_bucket[MAX_E];   // edge id per slot
__device__ int   g_bsrc[MAX_E];     // src node per slot (kills a dependent load)
__device__ float g_outscale[MAX_N];
__device__ float g_inscale[MAX_N];
__device__ int   g_total;

// ---------------- K1: zero counters ----------------------------------------
__global__ void zero_kernel(int N) {
    int i = blockIdx.x * blockDim.x + threadIdx.x;
    if (i < N) {
        g_outdeg[i] = 0;
        g_indeg[i]  = 0;
        g_cursor[i] = 0;
    }
    if (i == 0) g_total = 0;
}

// ---------------- K2: degree histograms -------------------------------------
__global__ void degree_kernel(const int* __restrict__ src,
                              const int* __restrict__ dst, int E) {
    int e = blockIdx.x * blockDim.x + threadIdx.x;
    if (e < E) {
        atomicAdd(&g_outdeg[src[e]], 1);
        atomicAdd(&g_indeg[dst[e]], 1);
    }
}

// ---------------- K3: per-node range allocation + scales ---------------------
// Bucket ranges need only be disjoint & contiguous per node, not node-ordered:
// warp shuffle-scan + one atomicAdd per warp.
__global__ void offsets_kernel(int N) {
    int i = blockIdx.x * blockDim.x + threadIdx.x;
    int lane = threadIdx.x & 31;
    int v = (i < N) ? g_indeg[i] : 0;
    if (i < N) {
        g_inscale[i]  = rsqrtf(fmaxf((float)v, 1.0f));
        g_outscale[i] = rsqrtf(fmaxf((float)g_outdeg[i], 1.0f));
    }
    int incl = v;
#pragma unroll
    for (int off = 1; off < 32; off <<= 1) {
        int x = __shfl_up_sync(0xffffffffu, incl, off);
        if (lane >= off) incl += x;
    }
    int warp_sum = __shfl_sync(0xffffffffu, incl, 31);
    int base = 0;
    if (lane == 31) base = atomicAdd(&g_total, warp_sum);
    base = __shfl_sync(0xffffffffu, base, 31);
    if (i < N) g_starts[i] = base + incl - v;
}

// ---------------- K4: bucket fill (counting sort by dst) --------------------
__global__ void bucket_kernel(const int* __restrict__ src,
                              const int* __restrict__ dst, int E) {
    int e = blockIdx.x * blockDim.x + threadIdx.x;
    if (e < E) {
        int d = dst[e];
        int pos = atomicAdd(&g_cursor[d], 1) + g_starts[d];
        g_bucket[pos] = e;
        g_bsrc[pos]   = src[e];
    }
}

// ---------------- K5: pull-style gather (warp per dst node), unroll x2 -------
// h[n,0:192] = is * sum_e os[src]*feat[src];  h[n,192:256] = is * sum_e edge[e]
// Epilogue writes the bf16 hi/lo split directly (GEMM stages raw bytes).
__global__ void gather_kernel(const float* __restrict__ feat,
                              const float* __restrict__ edge_feat,
                              int N) {
    int warp = (blockIdx.x * blockDim.x + threadIdx.x) >> 5;
    int lane = threadIdx.x & 31;
    if (warp >= N) return;

    int beg = g_starts[warp];
    int cnt = g_indeg[warp];

    float4 accA = make_float4(0.f, 0.f, 0.f, 0.f);
    float4 accB = make_float4(0.f, 0.f, 0.f, 0.f);

    int i = 0;
    for (; i + 1 < cnt; i += 2) {
        int p  = beg + i;
        int e0 = g_bucket[p],   e1 = g_bucket[p + 1];
        int s0 = g_bsrc[p],     s1 = g_bsrc[p + 1];
        float c0 = g_outscale[s0], c1 = g_outscale[s1];
        const float4* f0 = (const float4*)(feat + (size_t)s0 * D_NODE);
        const float4* f1 = (const float4*)(feat + (size_t)s1 * D_NODE);
        float4 a0 = __ldg(&f0[lane]);
        float4 a1 = __ldg(&f1[lane]);
        accA.x += a0.x * c0 + a1.x * c1;
        accA.y += a0.y * c0 + a1.y * c1;
        accA.z += a0.z * c0 + a1.z * c1;
        accA.w += a0.w * c0 + a1.w * c1;

        float4 b0, b1; float d0, d1;
        if (lane < 16) {
            b0 = __ldg(&f0[32 + lane]); d0 = c0;
            b1 = __ldg(&f1[32 + lane]); d1 = c1;
        } else {
            b0 = __ldg(&((const float4*)(edge_feat + (size_t)e0 * D_EDGE))[lane - 16]); d0 = 1.f;
            b1 = __ldg(&((const float4*)(edge_feat + (size_t)e1 * D_EDGE))[lane - 16]); d1 = 1.f;
        }
        accB.x += b0.x * d0 + b1.x * d1;
        accB.y += b0.y * d0 + b1.y * d1;
        accB.z += b0.z * d0 + b1.z * d1;
        accB.w += b0.w * d0 + b1.w * d1;
    }
    if (i < cnt) {
        int p  = beg + i;
        int e0 = g_bucket[p];
        int s0 = g_bsrc[p];
        float c0 = g_outscale[s0];
        const float4* f0 = (const float4*)(feat + (size_t)s0 * D_NODE);
        float4 a0 = __ldg(&f0[lane]);
        accA.x += a0.x * c0; accA.y += a0.y * c0;
        accA.z += a0.z * c0; accA.w += a0.w * c0;
        float4 b0; float d0;
        if (lane < 16) { b0 = __ldg(&f0[32 + lane]); d0 = c0; }
        else { b0 = __ldg(&((const float4*)(edge_feat + (size_t)e0 * D_EDGE))[lane - 16]); d0 = 1.f; }
        accB.x += b0.x * d0; accB.y += b0.y * d0;
        accB.z += b0.z * d0; accB.w += b0.w * d0;
    }

    float is = g_inscale[warp];
    accA.x *= is; accA.y *= is; accA.z *= is; accA.w *= is;
    accB.x *= is; accB.y *= is; accB.z *= is; accB.w *= is;

    // split into bf16 hi/lo and store: accA -> cols 4l..4l+3, accB -> 128+4l..
    size_t rb = (size_t)warp * D_IN;
    __nv_bfloat162* hh = (__nv_bfloat162*)(g_hh + rb);
    __nv_bfloat162* hl = (__nv_bfloat162*)(g_hl + rb);

    __nv_bfloat162 p0, p1, q0, q1;
    p0.x = __float2bfloat16(accA.x); p0.y = __float2bfloat16(accA.y);
    p1.x = __float2bfloat16(accA.z); p1.y = __float2bfloat16(accA.w);
    hh[2 * lane]     = p0;
    hh[2 * lane + 1] = p1;
    q0.x = __float2bfloat16(accA.x - __bfloat162float(p0.x));
    q0.y = __float2bfloat16(accA.y - __bfloat162float(p0.y));
    q1.x = __float2bfloat16(accA.z - __bfloat162float(p1.x));
    q1.y = __float2bfloat16(accA.w - __bfloat162float(p1.y));
    hl[2 * lane]     = q0;
    hl[2 * lane + 1] = q1;

    p0.x = __float2bfloat16(accB.x); p0.y = __float2bfloat16(accB.y);
    p1.x = __float2bfloat16(accB.z); p1.y = __float2bfloat16(accB.w);
    hh[64 + 2 * lane]     = p0;
    hh[64 + 2 * lane + 1] = p1;
    q0.x = __float2bfloat16(accB.x - __bfloat162float(p0.x));
    q0.y = __float2bfloat16(accB.y - __bfloat162float(p0.y));
    q1.x = __float2bfloat16(accB.z - __bfloat162float(p1.x));
    q1.y = __float2bfloat16(accB.w - __bfloat162float(p1.y));
    hl[64 + 2 * lane]     = q0;
    hl[64 + 2 * lane + 1] = q1;
}

// ---------------- K5b: split W into bf16 hi/lo -------------------------------
__global__ void wsplit_kernel(const float* __restrict__ W) {
    int i = blockIdx.x * blockDim.x + threadIdx.x;
    if (i < D_IN * D_OUT) {
        float v = W[i];
        __nv_bfloat16 hi = __float2bfloat16(v);
        g_wh[i] = hi;
        g_wl[i] = __float2bfloat16(v - __bfloat162float(hi));
    }
}

// ---------------- K6: GEMM out = h @ W + bias (split-bf16 3-pass) ------------
// Block tile 128x128, 8 warps (4 M x 2 N), warp tile 32x64, KCHUNK=32.
// Register double-buffering of global loads; bias folded into acc init;
// fragments store straight to global (M % 16 == 0 so per-frag guards exact).
#define APAD 40
#define BPAD 136

__global__ __launch_bounds__(256, 1) void gemm_kernel(const float* __restrict__ bias,
                                                      float* __restrict__ out, int M) {
    __shared__ __align__(16) __nv_bfloat16 sAh[128 * APAD];
    __shared__ __align__(16) __nv_bfloat16 sAl[128 * APAD];
    __shared__ __align__(16) __nv_bfloat16 sBh[32 * BPAD];
    __shared__ __align__(16) __nv_bfloat16 sBl[32 * BPAD];
    __shared__ __align__(16) float sBias[16 * BPAD];

    int t = threadIdx.x;
    int warpId = t >> 5;
    int wm = warpId & 3;        // 4 positions x 32 rows
    int wn = warpId >> 2;       // 2 positions x 64 cols
    int m0 = blockIdx.x * 128;
    int n0 = blockIdx.y * 128;

    // bias tile, replicated over 16 rows (accumulator-fragment init source)
#pragma unroll
    for (int r = 0; r < 8; r++) {
        int p = t + 256 * r;
        int row = p >> 7, col = p & 127;
        sBias[row * BPAD + col] = bias[n0 + col];
    }
    __syncthreads();

    wmma::fragment<wmma::accumulator, 16, 16, 16, float> acc[2][4];
#pragma unroll
    for (int i = 0; i < 2; i++)
#pragma unroll
        for (int j = 0; j < 4; j++)
            wmma::load_matrix_sync(acc[i][j], sBias + wn * 64 + j * 16, BPAD,
                                   wmma::mem_row_major);

    const uint4* GAh = (const uint4*)g_hh;
    const uint4* GAl = (const uint4*)g_hl;
    const uint4* GBh = (const uint4*)g_wh;
    const uint4* GBl = (const uint4*)g_wl;
    const uint4 z4 = make_uint4(0, 0, 0, 0);

    uint4 rah[2], ral[2], rbh[2], rbl[2];

    // A chunk: 128 rows x 32 cols; per thread 2 uint4 per array.
    // p -> row = p>>2, colchunk = p&3 (8 bf16 each). uint4 row stride = 32.
    // B chunk: 32 rows x 128 cols; p -> row = p>>4, colchunk = p&15.
#define LOAD_CHUNK(kc)                                                          \
    {                                                                           \
        _Pragma("unroll")                                                       \
        for (int u = 0; u < 2; u++) {                                           \
            int p = t + 256 * u;                                                \
            int row = p >> 2, cch = p & 3;                                      \
            int gm = m0 + row;                                                  \
            size_t gi = (size_t)gm * 32 + ((kc) >> 3) + cch;                    \
            rah[u] = (gm < M) ? GAh[gi] : z4;                                   \
            ral[u] = (gm < M) ? GAl[gi] : z4;                                   \
            int rowb = p >> 4, cchb = p & 15;                                   \
            size_t gj = (size_t)((kc) + rowb) * 32 + (n0 >> 3) + cchb;          \
            rbh[u] = GBh[gj];                                                   \
            rbl[u] = GBl[gj];                                                   \
        }                                                                       \
    }

#define STORE_CHUNK()                                                           \
    {                                                                           \
        _Pragma("unroll")                                                       \
        for (int u = 0; u < 2; u++) {                                           \
            int p = t + 256 * u;                                                \
            int row = p >> 2, cch = p & 3;                                      \
            *(uint4*)(sAh + row * APAD + cch * 8) = rah[u];                     \
            *(uint4*)(sAl + row * APAD + cch * 8) = ral[u];                     \
            int rowb = p >> 4, cchb = p & 15;                                   \
            *(uint4*)(sBh + rowb * BPAD + cchb * 8) = rbh[u];                   \
            *(uint4*)(sBl + rowb * BPAD + cchb * 8) = rbl[u];                   \
        }                                                                       \
    }

    LOAD_CHUNK(0);
#pragma unroll
    for (int kci = 0; kci < 8; kci++) {
        __syncthreads();
        STORE_CHUNK();
        __syncthreads();
        if (kci < 7) LOAD_CHUNK((kci + 1) * 32);

#pragma unroll
        for (int kk = 0; kk < 32; kk += 16) {
            wmma::fragment<wmma::matrix_a, 16, 16, 16, __nv_bfloat16, wmma::row_major> fah[2], fal[2];
            wmma::fragment<wmma::matrix_b, 16, 16, 16, __nv_bfloat16, wmma::row_major> fbh[4], fbl[4];
#pragma unroll
            for (int i = 0; i < 2; i++) {
                wmma::load_matrix_sync(fah[i], sAh + (wm * 32 + i * 16) * APAD + kk, APAD);
                wmma::load_matrix_sync(fal[i], sAl + (wm * 32 + i * 16) * APAD + kk, APAD);
            }
#pragma unroll
            for (int j = 0; j < 4; j++) {
                wmma::load_matrix_sync(fbh[j], sBh + kk * BPAD + wn * 64 + j * 16, BPAD);
                wmma::load_matrix_sync(fbl[j], sBl + kk * BPAD + wn * 64 + j * 16, BPAD);
            }
#pragma unroll
            for (int i = 0; i < 2; i++)
#pragma unroll
                for (int j = 0; j < 4; j++) {
                    wmma::mma_sync(acc[i][j], fal[i], fbh[j], acc[i][j]);
                    wmma::mma_sync(acc[i][j], fah[i], fbl[j], acc[i][j]);
                    wmma::mma_sync(acc[i][j], fah[i], fbh[j], acc[i][j]);
                }
        }
    }

    // epilogue: fragments straight to global (bias already inside)
#pragma unroll
    for (int i = 0; i < 2; i++) {
        int gm = m0 + wm * 32 + i * 16;
        if (gm < M) {
#pragma unroll
            for (int j = 0; j < 4; j++)
                wmma::store_matrix_sync(out + (size_t)gm * D_OUT + n0 + wn * 64 + j * 16,
                                        acc[i][j], D_OUT, wmma::mem_row_major);
        }
    }
}

// ---------------- launch -----------------------------------------------------
extern "C" void kernel_launch(void* const* d_in, const int* in_sizes, int n_in,
                              void* d_out, int out_size) {
    const float* feat      = (const float*)d_in[0];
    const float* edge_feat = (const float*)d_in[1];
    const int*   src       = (const int*)d_in[2];
    const int*   dst       = (const int*)d_in[3];
    const float* weight    = (const float*)d_in[4];
    const float* bias      = (const float*)d_in[5];
    float* out = (float*)d_out;

    int N = in_sizes[0] / D_NODE;   // 50000
    int E = in_sizes[2];            // 800000

    zero_kernel<<<(N + 255) / 256, 256>>>(N);
    degree_kernel<<<(E + 255) / 256, 256>>>(src, dst, E);
    offsets_kernel<<<(N + 255) / 256, 256>>>(N);
    bucket_kernel<<<(E + 255) / 256, 256>>>(src, dst, E);
    wsplit_kernel<<<(D_IN * D_OUT + 255) / 256, 256>>>(weight);
    gather_kernel<<<(N * 32 + 255) / 256, 256>>>(feat, edge_feat, N);

    dim3 ggrid((N + 127) / 128, D_OUT / 128);
    gemm_kernel<<<ggrid, 256>>>(bias, out, N);
}

// round 10
// speedup vs baseline: 1.3957x; 1.0061x over previous
#include <cuda_runtime.h>
#include <cuda_bf16.h>
#include <mma.h>
#include <cstdint>

using namespace nvcuda;

#define MAX_N 50000
#define MAX_E 800000
#define D_NODE 192
#define D_EDGE 64
#define D_IN 256
#define D_OUT 256

// ---------------- scratch (device globals: no allocations allowed) ----------
__device__ __nv_bfloat16 g_wh[D_IN * D_OUT];   // hi split of W [k][n]
__device__ __nv_bfloat16 g_wl[D_IN * D_OUT];   // lo split of W [k][n]
__device__ int   g_outdeg[MAX_N];
__device__ int   g_indeg[MAX_N];
__device__ int   g_starts[MAX_N];
__device__ int   g_cursor[MAX_N];
__device__ int2  g_bpair[MAX_E];    // (edge id, src node) per slot
__device__ float g_outscale[MAX_N];
__device__ float g_inscale[MAX_N];
__device__ int   g_total;

// ---------------- K1: zero counters ----------------------------------------
__global__ void zero_kernel(int N) {
    int i = blockIdx.x * blockDim.x + threadIdx.x;
    if (i < N) {
        g_outdeg[i] = 0;
        g_indeg[i]  = 0;
    }
    if (i == 0) g_total = 0;
}

// ---------------- K2: degree histograms -------------------------------------
__global__ void degree_kernel(const int* __restrict__ src,
                              const int* __restrict__ dst, int E) {
    int e = blockIdx.x * blockDim.x + threadIdx.x;
    if (e < E) {
        atomicAdd(&g_outdeg[src[e]], 1);
        atomicAdd(&g_indeg[dst[e]], 1);
    }
}

// ---------------- K3: per-node range allocation + scales ---------------------
// Ranges need only be disjoint & contiguous per node, not node-ordered:
// warp shuffle-scan + one atomicAdd per warp.
__global__ void offsets_kernel(int N) {
    int i = blockIdx.x * blockDim.x + threadIdx.x;
    int lane = threadIdx.x & 31;
    int v = (i < N) ? g_indeg[i] : 0;
    if (i < N) {
        g_inscale[i]  = rsqrtf(fmaxf((float)v, 1.0f));
        g_outscale[i] = rsqrtf(fmaxf((float)g_outdeg[i], 1.0f));
    }
    int incl = v;
#pragma unroll
    for (int off = 1; off < 32; off <<= 1) {
        int x = __shfl_up_sync(0xffffffffu, incl, off);
        if (lane >= off) incl += x;
    }
    int warp_sum = __shfl_sync(0xffffffffu, incl, 31);
    int base = 0;
    if (lane == 31) base = atomicAdd(&g_total, warp_sum);
    base = __shfl_sync(0xffffffffu, base, 31);
    if (i < N) {
        int st = base + incl - v;
        g_starts[i] = st;
        g_cursor[i] = st;      // bucket_kernel atomicAdds this directly
    }
}

// ---------------- K4: bucket fill (counting sort by dst) --------------------
__global__ void bucket_kernel(const int* __restrict__ src,
                              const int* __restrict__ dst, int E) {
    int e = blockIdx.x * blockDim.x + threadIdx.x;
    if (e < E) {
        int d = dst[e];
        int pos = atomicAdd(&g_cursor[d], 1);
        g_bpair[pos] = make_int2(e, src[e]);
    }
}

// ---------------- K4b: split W into bf16 hi/lo ([k][n], no transpose) --------
__global__ void wsplit_kernel(const float* __restrict__ W) {
    int i = blockIdx.x * blockDim.x + threadIdx.x;
    if (i < D_IN * D_OUT) {
        float v = W[i];
        __nv_bfloat16 hi = __float2bfloat16(v);
        g_wh[i] = hi;
        g_wl[i] = __float2bfloat16(v - __bfloat162float(hi));
    }
}

// ---------------- K5: FUSED gather + GEMM ------------------------------------
// One CTA = 128 nodes x full N=256. 512 threads = 16 warps.
// Phase 1: warp gathers 8 nodes, writes bf16 hi/lo splits of
//   h = in_scale * [ sum out_scale*feat[src] | sum edge_feat ]
// straight into resident A smem tiles (K=256 fully staged).
// Phase 2: split-bf16 3-pass wmma GEMM; B (W) streamed per 32-K chunk with
// register double-buffering; bias folded into accumulator init; fragments
// store straight to global (M % 16 == 0 so per-frag guards are exact).
#define APAD 264            // A smem stride (bf16), 528B rows (16B-mult, not 128B-mult)
#define BPAD 264            // B smem stride (bf16)
#define A_BYTES  (128 * APAD * 2)              // 67584 per array
#define B_BYTES  (32 * BPAD * 2)               // 16896 per array
#define FUSED_SMEM (2 * A_BYTES + 2 * B_BYTES) // 168960

__global__ __launch_bounds__(512, 1) void fused_kernel(const float* __restrict__ feat,
                                                       const float* __restrict__ edge_feat,
                                                       const float* __restrict__ bias,
                                                       float* __restrict__ out,
                                                       int N) {
    extern __shared__ __align__(16) unsigned char smem[];
    __nv_bfloat16* sAh = (__nv_bfloat16*)smem;
    __nv_bfloat16* sAl = (__nv_bfloat16*)(smem + A_BYTES);
    __nv_bfloat16* sBh = (__nv_bfloat16*)(smem + 2 * A_BYTES);
    __nv_bfloat16* sBl = (__nv_bfloat16*)(smem + 2 * A_BYTES + B_BYTES);
    float* sBias = (float*)sBh;                // overlay; consumed before B store

    int t = threadIdx.x;
    int warpId = t >> 5, lane = t & 31;
    int m0 = blockIdx.x * 128;

    // ---------------- phase 1: gather 8 nodes per warp ----------------------
#pragma unroll 1
    for (int j = 0; j < 8; j++) {
        int r = warpId * 8 + j;
        int node = m0 + r;
        int beg = 0, cnt = 0;
        if (node < N) { beg = g_starts[node]; cnt = g_indeg[node]; }

        float4 accA = make_float4(0.f, 0.f, 0.f, 0.f);
        float4 accB = make_float4(0.f, 0.f, 0.f, 0.f);

        int i = 0;
        for (; i + 1 < cnt; i += 2) {
            int2 p0 = g_bpair[beg + i];
            int2 p1 = g_bpair[beg + i + 1];
            int e0 = p0.x, s0 = p0.y;
            int e1 = p1.x, s1 = p1.y;
            float c0 = g_outscale[s0], c1 = g_outscale[s1];
            const float4* f0 = (const float4*)(feat + (size_t)s0 * D_NODE);
            const float4* f1 = (const float4*)(feat + (size_t)s1 * D_NODE);
            float4 a0 = __ldg(&f0[lane]);
            float4 a1 = __ldg(&f1[lane]);
            accA.x += a0.x * c0 + a1.x * c1;
            accA.y += a0.y * c0 + a1.y * c1;
            accA.z += a0.z * c0 + a1.z * c1;
            accA.w += a0.w * c0 + a1.w * c1;

            float4 b0, b1; float d0, d1;
            if (lane < 16) {
                b0 = __ldg(&f0[32 + lane]); d0 = c0;
                b1 = __ldg(&f1[32 + lane]); d1 = c1;
            } else {
                b0 = __ldg(&((const float4*)(edge_feat + (size_t)e0 * D_EDGE))[lane - 16]); d0 = 1.f;
                b1 = __ldg(&((const float4*)(edge_feat + (size_t)e1 * D_EDGE))[lane - 16]); d1 = 1.f;
            }
            accB.x += b0.x * d0 + b1.x * d1;
            accB.y += b0.y * d0 + b1.y * d1;
            accB.z += b0.z * d0 + b1.z * d1;
            accB.w += b0.w * d0 + b1.w * d1;
        }
        if (i < cnt) {
            int2 pp = g_bpair[beg + i];
            int e0 = pp.x, s0 = pp.y;
            float c0 = g_outscale[s0];
            const float4* f0 = (const float4*)(feat + (size_t)s0 * D_NODE);
            float4 a0 = __ldg(&f0[lane]);
            accA.x += a0.x * c0; accA.y += a0.y * c0;
            accA.z += a0.z * c0; accA.w += a0.w * c0;
            float4 b0; float d0;
            if (lane < 16) { b0 = __ldg(&f0[32 + lane]); d0 = c0; }
            else { b0 = __ldg(&((const float4*)(edge_feat + (size_t)e0 * D_EDGE))[lane - 16]); d0 = 1.f; }
            accB.x += b0.x * d0; accB.y += b0.y * d0;
            accB.z += b0.z * d0; accB.w += b0.w * d0;
        }

        float is = (node < N) ? g_inscale[node] : 0.f;
        accA.x *= is; accA.y *= is; accA.z *= is; accA.w *= is;
        accB.x *= is; accB.y *= is; accB.z *= is; accB.w *= is;

        // split + store into resident A tiles: cols 4l.. and 128+4l..
        __nv_bfloat162 h0, h1, l0, l1;
        h0.x = __float2bfloat16(accA.x); h0.y = __float2bfloat16(accA.y);
        h1.x = __float2bfloat16(accA.z); h1.y = __float2bfloat16(accA.w);
        l0.x = __float2bfloat16(accA.x - __bfloat162float(h0.x));
        l0.y = __float2bfloat16(accA.y - __bfloat162float(h0.y));
        l1.x = __float2bfloat16(accA.z - __bfloat162float(h1.x));
        l1.y = __float2bfloat16(accA.w - __bfloat162float(h1.y));
        int baseA = r * APAD + 4 * lane;
        *(uint2*)(sAh + baseA) = make_uint2(*(uint32_t*)&h0, *(uint32_t*)&h1);
        *(uint2*)(sAl + baseA) = make_uint2(*(uint32_t*)&l0, *(uint32_t*)&l1);

        h0.x = __float2bfloat16(accB.x); h0.y = __float2bfloat16(accB.y);
        h1.x = __float2bfloat16(accB.z); h1.y = __float2bfloat16(accB.w);
        l0.x = __float2bfloat16(accB.x - __bfloat162float(h0.x));
        l0.y = __float2bfloat16(accB.y - __bfloat162float(h0.y));
        l1.x = __float2bfloat16(accB.z - __bfloat162float(h1.x));
        l1.y = __float2bfloat16(accB.w - __bfloat162float(h1.y));
        int baseB = r * APAD + 128 + 4 * lane;
        *(uint2*)(sAh + baseB) = make_uint2(*(uint32_t*)&h0, *(uint32_t*)&h1);
        *(uint2*)(sAl + baseB) = make_uint2(*(uint32_t*)&l0, *(uint32_t*)&l1);
    }

    // bias tile, replicated over 16 rows (accumulator-fragment init source)
#pragma unroll
    for (int u = 0; u < 8; u++) {
        int p = t + 512 * u;                    // 0..4095
        int row = p >> 8, col = p & 255;
        sBias[row * BPAD + col] = __ldg(&bias[col]);
    }
    __syncthreads();

    // ---------------- phase 2: GEMM -----------------------------------------
    int wm = warpId & 3;        // 4 positions x 32 rows
    int wn = warpId >> 2;       // 4 positions x 64 cols

    wmma::fragment<wmma::accumulator, 16, 16, 16, float> acc[2][4];
#pragma unroll
    for (int i = 0; i < 2; i++)
#pragma unroll
        for (int j = 0; j < 4; j++)
            wmma::load_matrix_sync(acc[i][j], sBias + wn * 64 + j * 16, BPAD,
                                   wmma::mem_row_major);

    const uint4* GBh = (const uint4*)g_wh;
    const uint4* GBl = (const uint4*)g_wl;
    uint4 rbh[2], rbl[2];

    // B chunk: 32 k-rows x 256 n-cols = 1024 uint4 per array; 2/thread.
#define LOADB(kc)                                                               \
    {                                                                           \
        _Pragma("unroll")                                                       \
        for (int u = 0; u < 2; u++) {                                           \
            int p = t + 512 * u;                                                \
            int row = p >> 5, c8 = p & 31;                                      \
            size_t gi = (size_t)((kc) + row) * 32 + c8;                         \
            rbh[u] = GBh[gi];                                                   \
            rbl[u] = GBl[gi];                                                   \
        }                                                                       \
    }
#define STOREB()                                                                \
    {                                                                           \
        _Pragma("unroll")                                                       \
        for (int u = 0; u < 2; u++) {                                           \
            int p = t + 512 * u;                                                \
            int row = p >> 5, c8 = p & 31;                                      \
            *(uint4*)(sBh + row * BPAD + c8 * 8) = rbh[u];                      \
            *(uint4*)(sBl + row * BPAD + c8 * 8) = rbl[u];                      \
        }                                                                       \
    }

    LOADB(0);
#pragma unroll 1
    for (int c = 0; c < 8; c++) {
        __syncthreads();             // prior reads (incl. bias) done before overwrite
        STOREB();
        __syncthreads();
        if (c < 7) LOADB((c + 1) * 32);
        int kc = c * 32;

#pragma unroll
        for (int kk = 0; kk < 32; kk += 16) {
            wmma::fragment<wmma::matrix_a, 16, 16, 16, __nv_bfloat16, wmma::row_major> fah[2], fal[2];
            wmma::fragment<wmma::matrix_b, 16, 16, 16, __nv_bfloat16, wmma::row_major> fbh[4], fbl[4];
#pragma unroll
            for (int i = 0; i < 2; i++) {
                wmma::load_matrix_sync(fah[i], sAh + (wm * 32 + i * 16) * APAD + kc + kk, APAD);
                wmma::load_matrix_sync(fal[i], sAl + (wm * 32 + i * 16) * APAD + kc + kk, APAD);
            }
#pragma unroll
            for (int j = 0; j < 4; j++) {
                wmma::load_matrix_sync(fbh[j], sBh + kk * BPAD + wn * 64 + j * 16, BPAD);
                wmma::load_matrix_sync(fbl[j], sBl + kk * BPAD + wn * 64 + j * 16, BPAD);
            }
#pragma unroll
            for (int i = 0; i < 2; i++)
#pragma unroll
                for (int j = 0; j < 4; j++) {
                    wmma::mma_sync(acc[i][j], fal[i], fbh[j], acc[i][j]);
                    wmma::mma_sync(acc[i][j], fah[i], fbl[j], acc[i][j]);
                    wmma::mma_sync(acc[i][j], fah[i], fbh[j], acc[i][j]);
                }
        }
    }

    // epilogue: fragments straight to global (bias already inside)
#pragma unroll
    for (int i = 0; i < 2; i++) {
        int gm = m0 + wm * 32 + i * 16;
        if (gm < N) {
#pragma unroll
            for (int j = 0; j < 4; j++)
                wmma::store_matrix_sync(out + (size_t)gm * D_OUT + wn * 64 + j * 16,
                                        acc[i][j], D_OUT, wmma::mem_row_major);
        }
    }
#undef LOADB
#undef STOREB
}

// ---------------- launch -----------------------------------------------------
extern "C" void kernel_launch(void* const* d_in, const int* in_sizes, int n_in,
                              void* d_out, int out_size) {
    const float* feat      = (const float*)d_in[0];
    const float* edge_feat = (const float*)d_in[1];
    const int*   src       = (const int*)d_in[2];
    const int*   dst       = (const int*)d_in[3];
    const float* weight    = (const float*)d_in[4];
    const float* bias      = (const float*)d_in[5];
    float* out = (float*)d_out;

    int N = in_sizes[0] / D_NODE;   // 50000
    int E = in_sizes[2];            // 800000

    zero_kernel<<<(N + 255) / 256, 256>>>(N);
    degree_kernel<<<(E + 255) / 256, 256>>>(src, dst, E);
    offsets_kernel<<<(N + 255) / 256, 256>>>(N);
    bucket_kernel<<<(E + 255) / 256, 256>>>(src, dst, E);
    wsplit_kernel<<<(D_IN * D_OUT + 255) / 256, 256>>>(weight);

    static int smem_set = 0;
    if (!smem_set) {
        cudaFuncSetAttribute(fused_kernel,
                             cudaFuncAttributeMaxDynamicSharedMemorySize, FUSED_SMEM);
        smem_set = 1;
    }
    fused_kernel<<<(N + 127) / 128, 512, FUSED_SMEM>>>(feat, edge_feat, bias, out, N);
}

// round 13
// speedup vs baseline: 1.5286x; 1.0952x over previous
#include <cuda_runtime.h>
#include <cuda_fp16.h>
#include <mma.h>
#include <cstdint>

using namespace nvcuda;

#define MAX_N 50000
#define MAX_E 800000
#define D_NODE 192
#define D_EDGE 64
#define D_IN 256
#define D_OUT 256

// ---------------- scratch (device globals: no allocations allowed) ----------
__device__ __half g_wh[D_IN * D_OUT];   // fp16 W [k][n]
__device__ int   g_outdeg[MAX_N];
__device__ int   g_indeg[MAX_N];
__device__ int   g_starts[MAX_N];
__device__ int   g_cursor[MAX_N];
__device__ int2  g_bpair[MAX_E];    // (edge id, src node) per slot
__device__ float g_outscale[MAX_N];
__device__ float g_inscale[MAX_N];
__device__ int   g_total;

// ---------------- K1: zero counters ----------------------------------------
__global__ void zero_kernel(int N) {
    int i = blockIdx.x * blockDim.x + threadIdx.x;
    if (i < N) {
        g_outdeg[i] = 0;
        g_indeg[i]  = 0;
    }
    if (i == 0) g_total = 0;
}

// ---------------- K2: degree histograms -------------------------------------
__global__ void degree_kernel(const int* __restrict__ src,
                              const int* __restrict__ dst, int E) {
    int e = blockIdx.x * blockDim.x + threadIdx.x;
    if (e < E) {
        atomicAdd(&g_outdeg[src[e]], 1);
        atomicAdd(&g_indeg[dst[e]], 1);
    }
}

// ---------------- K3: per-node range allocation + scales ---------------------
__global__ void offsets_kernel(int N) {
    int i = blockIdx.x * blockDim.x + threadIdx.x;
    int lane = threadIdx.x & 31;
    int v = (i < N) ? g_indeg[i] : 0;
    if (i < N) {
        g_inscale[i]  = rsqrtf(fmaxf((float)v, 1.0f));
        g_outscale[i] = rsqrtf(fmaxf((float)g_outdeg[i], 1.0f));
    }
    int incl = v;
#pragma unroll
    for (int off = 1; off < 32; off <<= 1) {
        int x = __shfl_up_sync(0xffffffffu, incl, off);
        if (lane >= off) incl += x;
    }
    int warp_sum = __shfl_sync(0xffffffffu, incl, 31);
    int base = 0;
    if (lane == 31) base = atomicAdd(&g_total, warp_sum);
    base = __shfl_sync(0xffffffffu, base, 31);
    if (i < N) {
        int st = base + incl - v;
        g_starts[i] = st;
        g_cursor[i] = st;
    }
}

// ---------------- K4: bucket fill (counting sort by dst) --------------------
__global__ void bucket_kernel(const int* __restrict__ src,
                              const int* __restrict__ dst, int E) {
    int e = blockIdx.x * blockDim.x + threadIdx.x;
    if (e < E) {
        int d = dst[e];
        int pos = atomicAdd(&g_cursor[d], 1);
        g_bpair[pos] = make_int2(e, src[e]);
    }
}

// ---------------- K4b: W -> fp16 --------------------------------------------
__global__ void wsplit_kernel(const float* __restrict__ W) {
    int i = blockIdx.x * blockDim.x + threadIdx.x;
    if (i < D_IN * D_OUT) g_wh[i] = __float2half_rn(W[i]);
}

// ---------------- K5: FUSED gather + GEMM ------------------------------------
// One CTA = 128 nodes x full N=256, 512 threads = 16 warps.
// Phase 1: warp gathers 8 nodes (unroll x4), splits h into fp16 hi/lo in smem.
// Phase 2: split-fp16 2-pass wmma GEMM: out = (Ah+Al) @ Bh + bias.
//   B error ~2^-11 rel (fp16 W rounding) -> overall rel_err ~2.5e-4 < 1e-3.
#define APAD 264
#define BPAD 264
#define A_BYTES  (128 * APAD * 2)              // 67584 per array
#define B_BYTES  (32 * BPAD * 2)               // 16896
#define FUSED_SMEM (2 * A_BYTES + B_BYTES)     // 152064

__global__ __launch_bounds__(512, 1) void fused_kernel(const float* __restrict__ feat,
                                                       const float* __restrict__ edge_feat,
                                                       const float* __restrict__ bias,
                                                       float* __restrict__ out,
                                                       int N) {
    extern __shared__ __align__(16) unsigned char smem[];
    __half* sAh = (__half*)smem;
    __half* sAl = (__half*)(smem + A_BYTES);
    __half* sBh = (__half*)(smem + 2 * A_BYTES);
    float* sBias = (float*)sBh;                // overlay: 16*BPAD*4 == B_BYTES

    int t = threadIdx.x;
    int warpId = t >> 5, lane = t & 31;
    int m0 = blockIdx.x * 128;

    // ---------------- phase 1: gather 8 nodes per warp, unroll x4 -----------
#pragma unroll 1
    for (int j = 0; j < 8; j++) {
        int r = warpId * 8 + j;
        int node = m0 + r;
        int beg = 0, cnt = 0;
        if (node < N) { beg = g_starts[node]; cnt = g_indeg[node]; }

        float4 accA = make_float4(0.f, 0.f, 0.f, 0.f);
        float4 accB = make_float4(0.f, 0.f, 0.f, 0.f);

        int i = 0;
        for (; i + 3 < cnt; i += 4) {
            int2 pr[4];
            float cs[4];
            const float4* fr[4];
#pragma unroll
            for (int u = 0; u < 4; u++) pr[u] = g_bpair[beg + i + u];
#pragma unroll
            for (int u = 0; u < 4; u++) cs[u] = g_outscale[pr[u].y];
#pragma unroll
            for (int u = 0; u < 4; u++)
                fr[u] = (const float4*)(feat + (size_t)pr[u].y * D_NODE);
            float4 a[4];
#pragma unroll
            for (int u = 0; u < 4; u++) a[u] = __ldg(&fr[u][lane]);
#pragma unroll
            for (int u = 0; u < 4; u++) {
                accA.x += a[u].x * cs[u];
                accA.y += a[u].y * cs[u];
                accA.z += a[u].z * cs[u];
                accA.w += a[u].w * cs[u];
            }
            float4 b[4]; float ds[4];
            if (lane < 16) {
#pragma unroll
                for (int u = 0; u < 4; u++) { b[u] = __ldg(&fr[u][32 + lane]); ds[u] = cs[u]; }
            } else {
#pragma unroll
                for (int u = 0; u < 4; u++) {
                    b[u] = __ldg(&((const float4*)(edge_feat + (size_t)pr[u].x * D_EDGE))[lane - 16]);
                    ds[u] = 1.f;
                }
            }
#pragma unroll
            for (int u = 0; u < 4; u++) {
                accB.x += b[u].x * ds[u];
                accB.y += b[u].y * ds[u];
                accB.z += b[u].z * ds[u];
                accB.w += b[u].w * ds[u];
            }
        }
        for (; i < cnt; i++) {
            int2 pp = g_bpair[beg + i];
            int e0 = pp.x, s0 = pp.y;
            float c0 = g_outscale[s0];
            const float4* f0 = (const float4*)(feat + (size_t)s0 * D_NODE);
            float4 a0 = __ldg(&f0[lane]);
            accA.x += a0.x * c0; accA.y += a0.y * c0;
            accA.z += a0.z * c0; accA.w += a0.w * c0;
            float4 b0; float d0;
            if (lane < 16) { b0 = __ldg(&f0[32 + lane]); d0 = c0; }
            else { b0 = __ldg(&((const float4*)(edge_feat + (size_t)e0 * D_EDGE))[lane - 16]); d0 = 1.f; }
            accB.x += b0.x * d0; accB.y += b0.y * d0;
            accB.z += b0.z * d0; accB.w += b0.w * d0;
        }

        float is = (node < N) ? g_inscale[node] : 0.f;
        accA.x *= is; accA.y *= is; accA.z *= is; accA.w *= is;
        accB.x *= is; accB.y *= is; accB.z *= is; accB.w *= is;

        // fp16 hi/lo split, store to resident A tiles: cols 4l.. and 128+4l..
        __half2 h0, h1, l0, l1;
        h0 = __floats2half2_rn(accA.x, accA.y);
        h1 = __floats2half2_rn(accA.z, accA.w);
        l0 = __floats2half2_rn(accA.x - __half2float(h0.x), accA.y - __half2float(h0.y));
        l1 = __floats2half2_rn(accA.z - __half2float(h1.x), accA.w - __half2float(h1.y));
        int baseA = r * APAD + 4 * lane;
        *(uint2*)(sAh + baseA) = make_uint2(*(uint32_t*)&h0, *(uint32_t*)&h1);
        *(uint2*)(sAl + baseA) = make_uint2(*(uint32_t*)&l0, *(uint32_t*)&l1);

        h0 = __floats2half2_rn(accB.x, accB.y);
        h1 = __floats2half2_rn(accB.z, accB.w);
        l0 = __floats2half2_rn(accB.x - __half2float(h0.x), accB.y - __half2float(h0.y));
        l1 = __floats2half2_rn(accB.z - __half2float(h1.x), accB.w - __half2float(h1.y));
        int baseB = r * APAD + 128 + 4 * lane;
        *(uint2*)(sAh + baseB) = make_uint2(*(uint32_t*)&h0, *(uint32_t*)&h1);
        *(uint2*)(sAl + baseB) = make_uint2(*(uint32_t*)&l0, *(uint32_t*)&l1);
    }

    // bias tile, replicated over 16 rows (accumulator-fragment init source)
#pragma unroll
    for (int u = 0; u < 8; u++) {
        int p = t + 512 * u;                    // 0..4095
        int row = p >> 8, col = p & 255;
        sBias[row * BPAD + col] = __ldg(&bias[col]);
    }
    __syncthreads();

    // ---------------- phase 2: GEMM -----------------------------------------
    int wm = warpId & 3;        // 4 positions x 32 rows
    int wn = warpId >> 2;       // 4 positions x 64 cols

    wmma::fragment<wmma::accumulator, 16, 16, 16, float> acc[2][4];
#pragma unroll
    for (int i = 0; i < 2; i++)
#pragma unroll
        for (int j = 0; j < 4; j++)
            wmma::load_matrix_sync(acc[i][j], sBias + wn * 64 + j * 16, BPAD,
                                   wmma::mem_row_major);

    const uint4* GBh = (const uint4*)g_wh;
    uint4 rbh[2];

    // B chunk: 32 k-rows x 256 n-cols fp16 = 1024 uint4; 2/thread.
#define LOADB(kc)                                                               \
    {                                                                           \
        _Pragma("unroll")                                                       \
        for (int u = 0; u < 2; u++) {                                           \
            int p = t + 512 * u;                                                \
            int row = p >> 5, c8 = p & 31;                                      \
            size_t gi = (size_t)((kc) + row) * 32 + c8;                         \
            rbh[u] = GBh[gi];                                                   \
        }                                                                       \
    }
#define STOREB()                                                                \
    {                                                                           \
        _Pragma("unroll")                                                       \
        for (int u = 0; u < 2; u++) {                                           \
            int p = t + 512 * u;                                                \
            int row = p >> 5, c8 = p & 31;                                      \
            *(uint4*)(sBh + row * BPAD + c8 * 8) = rbh[u];                      \
        }                                                                       \
    }

    LOADB(0);
#pragma unroll 1
    for (int c = 0; c < 8; c++) {
        __syncthreads();             // prior reads (incl. bias) done before overwrite
        STOREB();
        __syncthreads();
        if (c < 7) LOADB((c + 1) * 32);
        int kc = c * 32;

#pragma unroll
        for (int kk = 0; kk < 32; kk += 16) {
            wmma::fragment<wmma::matrix_a, 16, 16, 16, __half, wmma::row_major> fah[2], fal[2];
            wmma::fragment<wmma::matrix_b, 16, 16, 16, __half, wmma::row_major> fbh[4];
#pragma unroll
            for (int i = 0; i < 2; i++) {
                wmma::load_matrix_sync(fah[i], sAh + (wm * 32 + i * 16) * APAD + kc + kk, APAD);
                wmma::load_matrix_sync(fal[i], sAl + (wm * 32 + i * 16) * APAD + kc + kk, APAD);
            }
#pragma unroll
            for (int j = 0; j < 4; j++)
                wmma::load_matrix_sync(fbh[j], sBh + kk * BPAD + wn * 64 + j * 16, BPAD);
#pragma unroll
            for (int i = 0; i < 2; i++)
#pragma unroll
                for (int j = 0; j < 4; j++) {
                    wmma::mma_sync(acc[i][j], fal[i], fbh[j], acc[i][j]);
                    wmma::mma_sync(acc[i][j], fah[i], fbh[j], acc[i][j]);
                }
        }
    }

    // epilogue: fragments straight to global (bias already inside)
#pragma unroll
    for (int i = 0; i < 2; i++) {
        int gm = m0 + wm * 32 + i * 16;
        if (gm < N) {
#pragma unroll
            for (int j = 0; j < 4; j++)
                wmma::store_matrix_sync(out + (size_t)gm * D_OUT + wn * 64 + j * 16,
                                        acc[i][j], D_OUT, wmma::mem_row_major);
        }
    }
#undef LOADB
#undef STOREB
}

// ---------------- launch -----------------------------------------------------
extern "C" void kernel_launch(void* const* d_in, const int* in_sizes, int n_in,
                              void* d_out, int out_size) {
    const float* feat      = (const float*)d_in[0];
    const float* edge_feat = (const float*)d_in[1];
    const int*   src       = (const int*)d_in[2];
    const int*   dst       = (const int*)d_in[3];
    const float* weight    = (const float*)d_in[4];
    const float* bias      = (const float*)d_in[5];
    float* out = (float*)d_out;

    int N = in_sizes[0] / D_NODE;   // 50000
    int E = in_sizes[2];            // 800000

    zero_kernel<<<(N + 255) / 256, 256>>>(N);
    degree_kernel<<<(E + 255) / 256, 256>>>(src, dst, E);
    offsets_kernel<<<(N + 255) / 256, 256>>>(N);
    bucket_kernel<<<(E + 255) / 256, 256>>>(src, dst, E);
    wsplit_kernel<<<(D_IN * D_OUT + 255) / 256, 256>>>(weight);

    static int smem_set = 0;
    if (!smem_set) {
        cudaFuncSetAttribute(fused_kernel,
                             cudaFuncAttributeMaxDynamicSharedMemorySize, FUSED_SMEM);
        smem_set = 1;
    }
    fused_kernel<<<(N + 127) / 128, 512, FUSED_SMEM>>>(feat, edge_feat, bias, out, N);
}